// round 1
// baseline (speedup 1.0000x reference)
#include <cuda_runtime.h>
#include <math.h>

#define NC 60
#define ND 952
#define DD 2040
#define NG 17737
#define NF 881
#define GAMMA 8.7f
#define BN_EPS 1e-5f

// ------------------------- device scratch (no cudaMalloc allowed) ----------
__device__ float g_cellfeat[NC * NG];
__device__ float g_exp0[NC * DD];
__device__ float g_exp[NC * DD];
__device__ float g_fig0[ND * DD];
__device__ float g_fig[ND * DD];
__device__ float g_X[ND * DD];
__device__ float g_cellsum[NC * DD];
__device__ float g_drugsum[ND * DD];
__device__ float g_cellc[NC * DD];
__device__ float g_drugc[ND * DD];
__device__ float g_adjs[NC * ND];
__device__ float g_adjsT[ND * NC];
__device__ float g_shc[NC * NC];
__device__ float g_shd[ND * ND];
__device__ float g_corr[NC * ND];
__device__ float g_dx[NC], g_dc[NC], g_dy[ND], g_dd[ND];
__device__ float g_b4h[NC], g_a4h[ND];
__device__ float g_mu[DD], g_rstd[DD];
__device__ float g_lxx[NC], g_lyy[ND];

// ------------------------- small helpers -----------------------------------
__device__ __forceinline__ float blockReduceSum(float v, float* red) {
    int t = threadIdx.x;
    red[t] = v; __syncthreads();
    for (int s = blockDim.x >> 1; s > 0; s >>= 1) {
        if (t < s) red[t] += red[t + s];
        __syncthreads();
    }
    float r = red[0]; __syncthreads();
    return r;
}

__global__ void k_zero(float* p, int n) {
    for (int i = blockIdx.x * blockDim.x + threadIdx.x; i < n; i += gridDim.x * blockDim.x)
        p[i] = 0.f;
}

// rows 0..NC-1: adj row sums -> dx, dc. rows NC..2NC-1: cell_hyper rows -> b4h
__global__ void k_prep_cell(const float* __restrict__ adj, const float* __restrict__ ch) {
    __shared__ float red[256];
    int b = blockIdx.x;
    if (b < NC) {
        float s = 0.f;
        for (int j = threadIdx.x; j < ND; j += 256) s += adj[b * ND + j];
        s = blockReduceSum(s, red);
        if (threadIdx.x == 0) {
            float rs = s + 1.f;
            g_dx[b] = rsqrtf(rs);
            g_dc[b] = 1.f / rs + 1.f;
        }
    } else {
        int r = b - NC;
        float s = 0.f;
        for (int j = threadIdx.x; j < NC; j += 256) s += ch[r * NC + j];
        s = blockReduceSum(s, red);
        if (threadIdx.x == 0) g_b4h[r] = 1.f / (s + 1.f);
    }
}

__global__ void k_prep_drug_cols(const float* __restrict__ adj) {
    int d = blockIdx.x * blockDim.x + threadIdx.x;
    if (d < ND) {
        float s = 0.f;
        for (int c = 0; c < NC; c++) s += adj[c * ND + d];
        s += 1.f;
        g_dy[d] = rsqrtf(s);
        g_dd[d] = 1.f / s + 1.f;
    }
}

__global__ void k_prep_a4h(const float* __restrict__ dh) {
    __shared__ float red[256];
    int r = blockIdx.x;
    float s = 0.f;
    for (int j = threadIdx.x; j < ND; j += 256) s += dh[r * ND + j];
    s = blockReduceSum(s, red);
    if (threadIdx.x == 0) g_a4h[r] = 1.f / (s + 1.f);
}

__global__ void k_scale_adj(const float* __restrict__ adj) {
    for (int i = blockIdx.x * blockDim.x + threadIdx.x; i < NC * ND; i += gridDim.x * blockDim.x) {
        int c = i / ND, d = i % ND;
        float v = g_dx[c] * adj[i] * g_dy[d];
        g_adjs[i] = v;
        g_adjsT[d * NC + c] = v;
    }
}

__global__ void k_scale_sym(const float* __restrict__ src, const float* __restrict__ diag,
                            float* __restrict__ dst, int n) {
    for (int i = blockIdx.x * blockDim.x + threadIdx.x; i < n * n; i += gridDim.x * blockDim.x) {
        int r = i / n, c = i % n;
        dst[i] = diag[r] * src[i] * diag[c];
    }
}

// per-row z-normalization with ddof=1
__global__ void k_znorm(const float* __restrict__ x, float* __restrict__ y) {
    __shared__ float red[256];
    int r = blockIdx.x;
    float s = 0.f, ss = 0.f;
    for (int j = threadIdx.x; j < NG; j += 256) {
        float v = x[(size_t)r * NG + j];
        s += v; ss += v * v;
    }
    s = blockReduceSum(s, red);
    ss = blockReduceSum(ss, red);
    float mu = s / (float)NG;
    float var = (ss - (float)NG * mu * mu) / (float)(NG - 1);
    float inv = rsqrtf(var);
    for (int j = threadIdx.x; j < NG; j += 256)
        y[(size_t)r * NG + j] = (x[(size_t)r * NG + j] - mu) * inv;
}

// column-wise BN stats (biased var) over R rows of [R, DD]
__global__ void k_bnstats(const float* __restrict__ x, int R) {
    int d = blockIdx.x * blockDim.x + threadIdx.x;
    if (d < DD) {
        float s = 0.f, ss = 0.f;
        for (int r = 0; r < R; r++) {
            float v = x[(size_t)r * DD + d];
            s += v; ss += v * v;
        }
        float mu = s / (float)R;
        float var = ss / (float)R - mu * mu;
        g_mu[d] = mu;
        g_rstd[d] = rsqrtf(var + BN_EPS);
    }
}

__global__ void k_bnapply(const float* __restrict__ x, float* __restrict__ y,
                          const float* __restrict__ g, const float* __restrict__ b, int R) {
    for (int i = blockIdx.x * blockDim.x + threadIdx.x; i < R * DD; i += gridDim.x * blockDim.x) {
        int d = i % DD;
        y[i] = (x[i] - g_mu[d]) * g_rstd[d] * g[d] + b[d];
    }
}

// out[r,c] = diag[r] * in[r,c]
__global__ void k_rowscale(const float* __restrict__ in, const float* __restrict__ diag,
                           float* __restrict__ out, int R) {
    for (int i = blockIdx.x * blockDim.x + threadIdx.x; i < R * DD; i += gridDim.x * blockDim.x)
        out[i] = diag[i / DD] * in[i];
}

// dst = a - dst
__global__ void k_sub_from(const float* __restrict__ a, float* __restrict__ dst, int n) {
    for (int i = blockIdx.x * blockDim.x + threadIdx.x; i < n; i += gridDim.x * blockDim.x)
        dst[i] = a[i] - dst[i];
}

// t = relu((sum + b0+b1+b2+b3) * (base + 1)); center rows; lxx = sum sq
__global__ void k_finalize(const float* __restrict__ sum, const float* __restrict__ base,
                           const float* __restrict__ b_agg,
                           int i0, int i1, int i2, int i3,
                           float* __restrict__ outc, float* __restrict__ lxx) {
    __shared__ float sm[DD];
    __shared__ float red[256];
    int r = blockIdx.x;
    float loc = 0.f;
    for (int c = threadIdx.x; c < DD; c += 256) {
        float bs = b_agg[i0 * DD + c] + b_agg[i1 * DD + c] + b_agg[i2 * DD + c] + b_agg[i3 * DD + c];
        float h = sum[(size_t)r * DD + c] + bs;
        float t = h * (base[(size_t)r * DD + c] + 1.f);
        t = fmaxf(t, 0.f);
        sm[c] = t; loc += t;
    }
    float tot = blockReduceSum(loc, red);
    float mu = tot / (float)DD;
    float ss = 0.f;
    for (int c = threadIdx.x; c < DD; c += 256) {
        float v = sm[c] - mu;
        outc[(size_t)r * DD + c] = v;
        ss += v * v;
    }
    ss = blockReduceSum(ss, red);
    if (threadIdx.x == 0) lxx[r] = ss;
}

__global__ void k_sigout(float* __restrict__ out) {
    for (int i = blockIdx.x * blockDim.x + threadIdx.x; i < NC * ND; i += gridDim.x * blockDim.x) {
        int m = i / ND, n = i % ND;
        float corr = g_corr[i] * rsqrtf(g_lxx[m] * g_lyy[n]);
        out[i] = 1.f / (1.f + expf(-GAMMA * corr));
    }
}

// ------------------------- generic tiled SGEMM ------------------------------
// C[m,n] = sum_k A[m,k] * (TB ? B[n,k] : B[k,n])
// EPI 0: atomicAdd into C (pre-zeroed, supports split-K).  EPI 1: plain store (S must be 1).
template <int BM, int BN, int BK, int TM, int TN, bool TB, int EPI>
__global__ void __launch_bounds__(256) k_gemm(const float* __restrict__ A,
                                              const float* __restrict__ B,
                                              float* __restrict__ C,
                                              int M, int N, int K, int S) {
    __shared__ __align__(16) float As[BK][BM];
    __shared__ __align__(16) float Bs[BK][BN];
    const int tid = threadIdx.x;
    const int m0 = blockIdx.y * BM, n0 = blockIdx.x * BN;
    const int kchunk = (K + S - 1) / S;
    const int k0 = blockIdx.z * kchunk;
    const int k1 = min(K, k0 + kchunk);
    const int tx = tid % (BN / TN);
    const int ty = tid / (BN / TN);

    float acc[TM][TN];
#pragma unroll
    for (int i = 0; i < TM; i++)
#pragma unroll
        for (int j = 0; j < TN; j++) acc[i][j] = 0.f;

    for (int kt = k0; kt < k1; kt += BK) {
#pragma unroll
        for (int e = tid; e < BM * BK; e += 256) {
            int r = e / BK, c = e % BK;
            int gm = m0 + r, gk = kt + c;
            As[c][r] = (gm < M && gk < k1) ? A[(size_t)gm * K + gk] : 0.f;
        }
        if (TB) {
#pragma unroll
            for (int e = tid; e < BN * BK; e += 256) {
                int r = e / BK, c = e % BK;
                int gn = n0 + r, gk = kt + c;
                Bs[c][r] = (gn < N && gk < k1) ? B[(size_t)gn * K + gk] : 0.f;
            }
        } else {
#pragma unroll
            for (int e = tid; e < BN * BK; e += 256) {
                int r = e / BN, c = e % BN;
                int gk = kt + r, gn = n0 + c;
                Bs[r][c] = (gk < k1 && gn < N) ? B[(size_t)gk * N + gn] : 0.f;
            }
        }
        __syncthreads();
#pragma unroll
        for (int kk = 0; kk < BK; kk++) {
            float a[TM], b[TN];
#pragma unroll
            for (int i = 0; i < TM; i += 4)
                *reinterpret_cast<float4*>(&a[i]) =
                    *reinterpret_cast<const float4*>(&As[kk][ty * TM + i]);
#pragma unroll
            for (int j = 0; j < TN; j += 4)
                *reinterpret_cast<float4*>(&b[j]) =
                    *reinterpret_cast<const float4*>(&Bs[kk][tx * TN + j]);
#pragma unroll
            for (int i = 0; i < TM; i++)
#pragma unroll
                for (int j = 0; j < TN; j++) acc[i][j] = fmaf(a[i], b[j], acc[i][j]);
        }
        __syncthreads();
    }

    const int gm0 = m0 + ty * TM, gn0 = n0 + tx * TN;
#pragma unroll
    for (int i = 0; i < TM; i++) {
        int gm = gm0 + i;
        if (gm < M) {
#pragma unroll
            for (int j = 0; j < TN; j++) {
                int gn = gn0 + j;
                if (gn < N) {
                    size_t idx = (size_t)gm * N + gn;
                    if (EPI == 0) atomicAdd(&C[idx], acc[i][j]);
                    else C[idx] = acc[i][j];
                }
            }
        }
    }
}

// Config aliases:
//   big    : BM=128, BN=128, TM=8, TN=8  (M large)
//   skinny : BM= 64, BN=128, TM=4, TN=8  (M = 60)
static inline dim3 gemm_grid(int M, int N, int BM, int BN, int S) {
    return dim3((N + BN - 1) / BN, (M + BM - 1) / BM, S);
}

template <typename T>
static T* symp(const void* s) {
    void* p = nullptr;
    cudaGetSymbolAddress(&p, s);
    return (T*)p;
}

extern "C" void kernel_launch(void* const* d_in, const int* in_sizes, int n_in,
                              void* d_out, int out_size) {
    const float* adj        = (const float*)d_in[0];
    const float* cell_exprs = (const float*)d_in[1];
    const float* drug_fing  = (const float*)d_in[2];
    const float* cell_hyper = (const float*)d_in[3];
    const float* drug_hyper = (const float*)d_in[4];
    const float* W_agg      = (const float*)d_in[5];
    const float* b_agg      = (const float*)d_in[6];
    const float* ldd_w      = (const float*)d_in[7];
    // d_in[8] = ldd_b: cancelled by BatchNorm
    const float* lcc_w      = (const float*)d_in[9];
    // d_in[10] = lcc_b: cancelled by BatchNorm
    const float* bnd_g      = (const float*)d_in[11];
    const float* bnd_b      = (const float*)d_in[12];
    const float* bnc_g      = (const float*)d_in[13];
    const float* bnc_b      = (const float*)d_in[14];
    float* out = (float*)d_out;

    float* p_cellfeat = symp<float>(g_cellfeat);
    float* p_exp0     = symp<float>(g_exp0);
    float* p_exp      = symp<float>(g_exp);
    float* p_fig0     = symp<float>(g_fig0);
    float* p_fig      = symp<float>(g_fig);
    float* p_X        = symp<float>(g_X);
    float* p_cellsum  = symp<float>(g_cellsum);
    float* p_drugsum  = symp<float>(g_drugsum);
    float* p_cellc    = symp<float>(g_cellc);
    float* p_drugc    = symp<float>(g_drugc);
    float* p_adjs     = symp<float>(g_adjs);
    float* p_adjsT    = symp<float>(g_adjsT);
    float* p_shc      = symp<float>(g_shc);
    float* p_shd      = symp<float>(g_shd);
    float* p_corr     = symp<float>(g_corr);
    float* p_dc       = symp<float>(g_dc);
    float* p_dd       = symp<float>(g_dd);
    float* p_b4h      = symp<float>(g_b4h);
    float* p_a4h      = symp<float>(g_a4h);
    float* p_lxx      = symp<float>(g_lxx);
    float* p_lyy      = symp<float>(g_lyy);

    const int T = 256;
    // ---- zero accumulation targets
    k_zero<<<128, T>>>(p_exp0, NC * DD);
    k_zero<<<256, T>>>(p_fig0, ND * DD);
    k_zero<<<128, T>>>(p_cellsum, NC * DD);
    k_zero<<<256, T>>>(p_drugsum, ND * DD);
    k_zero<<<64, T>>>(p_corr, NC * ND);

    // ---- graph preprocessing
    k_prep_cell<<<2 * NC, T>>>(adj, cell_hyper);
    k_prep_drug_cols<<<(ND + T - 1) / T, T>>>(adj);
    k_prep_a4h<<<ND, T>>>(drug_hyper);
    k_scale_adj<<<64, T>>>(adj);
    k_scale_sym<<<16, T>>>(cell_hyper, p_b4h, p_shc, NC);
    k_scale_sym<<<512, T>>>(drug_hyper, p_a4h, p_shd, ND);

    // ---- z-norm of expressions
    k_znorm<<<NC, T>>>(cell_exprs, p_cellfeat);

    // ---- exp = BN(cellfeat @ lcc_w^T) : skinny NT, split-K 16
    k_gemm<64, 128, 8, 4, 8, true, 0><<<gemm_grid(NC, DD, 64, 128, 16), T>>>(
        p_cellfeat, lcc_w, p_exp0, NC, DD, NG, 16);
    k_bnstats<<<(DD + T - 1) / T, T>>>(p_exp0, NC);
    k_bnapply<<<128, T>>>(p_exp0, p_exp, bnc_g, bnc_b, NC);

    // ---- fig = BN(drug_finger @ ldd_w^T) : big NT, split-K 2
    k_gemm<128, 128, 8, 8, 8, true, 0><<<gemm_grid(ND, DD, 128, 128, 2), T>>>(
        drug_fing, ldd_w, p_fig0, ND, DD, NF, 2);
    k_bnstats<<<(DD + T - 1) / T, T>>>(p_fig0, ND);
    k_bnapply<<<512, T>>>(p_fig0, p_fig, bnd_g, bnd_b, ND);

    const float* W0 = W_agg + (size_t)0 * DD * DD;
    const float* W1 = W_agg + (size_t)1 * DD * DD;
    const float* W2 = W_agg + (size_t)2 * DD * DD;
    const float* W3 = W_agg + (size_t)3 * DD * DD;
    const float* W4 = W_agg + (size_t)4 * DD * DD;
    const float* W5 = W_agg + (size_t)5 * DD * DD;
    const float* W6 = W_agg + (size_t)6 * DD * DD;
    const float* W7 = W_agg + (size_t)7 * DD * DD;

    // ================= cell branches (M = 60), accumulate into cellsum ======
    // X0 = dc * exp
    k_rowscale<<<128, T>>>(p_exp, p_dc, p_X, NC);
    k_gemm<64, 128, 8, 4, 8, true, 0><<<gemm_grid(NC, DD, 64, 128, 8), T>>>(
        p_X, W0, p_cellsum, NC, DD, DD, 8);
    // X1 = agg_cell_lp @ fig  (NN, split-K 4, atomic)
    k_zero<<<128, T>>>(p_X, NC * DD);
    k_gemm<64, 128, 8, 4, 8, false, 0><<<gemm_grid(NC, DD, 64, 128, 4), T>>>(
        p_adjs, p_fig, p_X, NC, DD, ND, 4);
    k_gemm<64, 128, 8, 4, 8, true, 0><<<gemm_grid(NC, DD, 64, 128, 8), T>>>(
        p_X, W1, p_cellsum, NC, DD, DD, 8);
    // X4 = cell_hyper @ exp (NN, K=60, plain store)
    k_gemm<64, 128, 8, 4, 8, false, 1><<<gemm_grid(NC, DD, 64, 128, 1), T>>>(
        cell_hyper, p_exp, p_X, NC, DD, NC, 1);
    k_gemm<64, 128, 8, 4, 8, true, 0><<<gemm_grid(NC, DD, 64, 128, 8), T>>>(
        p_X, W4, p_cellsum, NC, DD, DD, 8);
    // X6 = exp - shc @ exp
    k_gemm<64, 128, 8, 4, 8, false, 1><<<gemm_grid(NC, DD, 64, 128, 1), T>>>(
        p_shc, p_exp, p_X, NC, DD, NC, 1);
    k_sub_from<<<128, T>>>(p_exp, p_X, NC * DD);
    k_gemm<64, 128, 8, 4, 8, true, 0><<<gemm_grid(NC, DD, 64, 128, 8), T>>>(
        p_X, W6, p_cellsum, NC, DD, DD, 8);

    // ================= drug branches (M = 952), accumulate into drugsum =====
    // X2 = dd * fig
    k_rowscale<<<512, T>>>(p_fig, p_dd, p_X, ND);
    k_gemm<128, 128, 8, 8, 8, true, 0><<<gemm_grid(ND, DD, 128, 128, 2), T>>>(
        p_X, W2, p_drugsum, ND, DD, DD, 2);
    // X3 = agg_drug_lp @ exp (NN, K=60, plain store)
    k_gemm<128, 128, 8, 8, 8, false, 1><<<gemm_grid(ND, DD, 128, 128, 1), T>>>(
        p_adjsT, p_exp, p_X, ND, DD, NC, 1);
    k_gemm<128, 128, 8, 8, 8, true, 0><<<gemm_grid(ND, DD, 128, 128, 2), T>>>(
        p_X, W3, p_drugsum, ND, DD, DD, 2);
    // X5 = drug_hyper @ fig (NN, split-K 2, atomic)
    k_zero<<<256, T>>>(p_X, ND * DD);
    k_gemm<128, 128, 8, 8, 8, false, 0><<<gemm_grid(ND, DD, 128, 128, 2), T>>>(
        drug_hyper, p_fig, p_X, ND, DD, ND, 2);
    k_gemm<128, 128, 8, 8, 8, true, 0><<<gemm_grid(ND, DD, 128, 128, 2), T>>>(
        p_X, W5, p_drugsum, ND, DD, DD, 2);
    // X7 = fig - shd @ fig
    k_zero<<<256, T>>>(p_X, ND * DD);
    k_gemm<128, 128, 8, 8, 8, false, 0><<<gemm_grid(ND, DD, 128, 128, 2), T>>>(
        p_shd, p_fig, p_X, ND, DD, ND, 2);
    k_sub_from<<<512, T>>>(p_fig, p_X, ND * DD);
    k_gemm<128, 128, 8, 8, 8, true, 0><<<gemm_grid(ND, DD, 128, 128, 2), T>>>(
        p_X, W7, p_drugsum, ND, DD, DD, 2);

    // ================= finalize: branch epilogue + relu + row-center ========
    k_finalize<<<NC, T>>>(p_cellsum, p_exp, b_agg, 0, 1, 4, 6, p_cellc, p_lxx);
    k_finalize<<<ND, T>>>(p_drugsum, p_fig, b_agg, 2, 3, 5, 7, p_drugc, p_lyy);

    // ================= correlation GEMM + scaled sigmoid ====================
    k_gemm<64, 128, 8, 4, 8, true, 0><<<gemm_grid(NC, ND, 64, 128, 8), T>>>(
        p_cellc, p_drugc, p_corr, NC, ND, DD, 8);
    k_sigout<<<64, T>>>(out);
}